// round 1
// baseline (speedup 1.0000x reference)
#include <cuda_runtime.h>
#include <math.h>

#define HW 4096
#define NB 2

// Scratch (module-load allocated, not runtime alloc)
__device__ float g_M [(size_t)NB * HW * HW];   // M[b][j][i]
__device__ float g_MT[(size_t)NB * HW * HW];   // M[b][i][j] (transpose)
__device__ float g_inv[4][NB * HW];            // 0:src3 1:tgt3 2:src4 3:tgt4

// ---------------------------------------------------------------------------
// Kernel 1: per-position inverse channel norms.  grid (32, 4) x 256
// ---------------------------------------------------------------------------
__global__ void norm_kernel(const float* __restrict__ s3, const float* __restrict__ t3,
                            const float* __restrict__ s4, const float* __restrict__ t4)
{
    int gid   = blockIdx.x * 256 + threadIdx.x;   // 0..8191 = b*4096 + pos
    int which = blockIdx.y;
    const float* x; int C;
    if      (which == 0) { x = s3; C = 1024; }
    else if (which == 1) { x = t3; C = 1024; }
    else if (which == 2) { x = s4; C = 2048; }
    else                 { x = t4; C = 2048; }

    int b = gid >> 12, pos = gid & (HW - 1);
    const float* p = x + (size_t)b * C * HW + pos;
    float ss0 = 0.f, ss1 = 0.f, ss2 = 0.f, ss3 = 0.f;
    for (int c = 0; c < C; c += 4) {
        float a0 = p[(size_t)(c + 0) * HW];
        float a1 = p[(size_t)(c + 1) * HW];
        float a2 = p[(size_t)(c + 2) * HW];
        float a3 = p[(size_t)(c + 3) * HW];
        ss0 = fmaf(a0, a0, ss0); ss1 = fmaf(a1, a1, ss1);
        ss2 = fmaf(a2, a2, ss2); ss3 = fmaf(a3, a3, ss3);
    }
    g_inv[which][gid] = rsqrtf((ss0 + ss1) + (ss2 + ss3) + 1e-6f);
}

// ---------------------------------------------------------------------------
// Kernel 2: tiled fp32 GEMM, C[j,i] = sum_c T[c,j]*S[c,i], epilogue fused.
//   MODE 0: M = relu(C3 * invT3[j] * invS3[i])
//   MODE 1: m = M * relu(C4 * invT4[j] * invS4[i]); M = m; MT = m
// 128x128 tile, BK=16, 256 threads, 8x8 per thread.
// ---------------------------------------------------------------------------
template<int MODE>
__global__ void __launch_bounds__(256, 2)
gemm_kernel(const float* __restrict__ Tg, const float* __restrict__ Sg, int C)
{
    __shared__ float Ts[16][128];
    __shared__ float Ss[16][128];

    const int b  = blockIdx.z;
    const int j0 = blockIdx.y * 128;
    const int i0 = blockIdx.x * 128;
    const float* Tb = Tg + (size_t)b * C * HW;
    const float* Sb = Sg + (size_t)b * C * HW;

    const int tid = threadIdx.x;
    const int tx  = tid & 15;    // i sub-tile
    const int ty  = tid >> 4;    // j sub-tile

    float acc[8][8];
#pragma unroll
    for (int u = 0; u < 8; ++u)
#pragma unroll
        for (int v = 0; v < 8; ++v) acc[u][v] = 0.f;

    for (int k0 = 0; k0 < C; k0 += 16) {
#pragma unroll
        for (int l = 0; l < 8; ++l) {
            int idx = tid + l * 256;
            int r = idx >> 7, col = idx & 127;
            Ts[r][col] = Tb[(size_t)(k0 + r) * HW + j0 + col];
            Ss[r][col] = Sb[(size_t)(k0 + r) * HW + i0 + col];
        }
        __syncthreads();
#pragma unroll
        for (int k = 0; k < 16; ++k) {
            float a[8], bv[8];
#pragma unroll
            for (int u = 0; u < 8; ++u) a[u]  = Ts[k][ty * 8 + u];
#pragma unroll
            for (int v = 0; v < 8; ++v) bv[v] = Ss[k][tx * 8 + v];
#pragma unroll
            for (int u = 0; u < 8; ++u)
#pragma unroll
                for (int v = 0; v < 8; ++v)
                    acc[u][v] = fmaf(a[u], bv[v], acc[u][v]);
        }
        __syncthreads();
    }

    const float* invT = g_inv[MODE == 0 ? 1 : 3] + b * HW;
    const float* invS = g_inv[MODE == 0 ? 0 : 2] + b * HW;
    float itv[8], isv[8];
#pragma unroll
    for (int u = 0; u < 8; ++u) itv[u] = invT[j0 + ty * 8 + u];
#pragma unroll
    for (int v = 0; v < 8; ++v) isv[v] = invS[i0 + tx * 8 + v];

#pragma unroll
    for (int u = 0; u < 8; ++u) {
        int j = j0 + ty * 8 + u;
        size_t rowo = ((size_t)b * HW + j) * HW;
#pragma unroll
        for (int v = 0; v < 8; ++v) {
            int i = i0 + tx * 8 + v;
            float c = acc[u][v] * itv[u] * isv[v];
            c = fmaxf(c, 0.f);
            if (MODE == 0) {
                g_M[rowo + i] = c;
            } else {
                float m = g_M[rowo + i] * c;
                g_M[rowo + i] = m;
                g_MT[((size_t)b * HW + i) * HW + j] = m;
            }
        }
    }
}

// ---------------------------------------------------------------------------
// Kernel 3: soft-argmax per column.  grid (4096, 2 batches, 2 dirs) x 256.
//   dir 0 (s2t): rows of MT   -> out offset 0
//   dir 1 (t2s): rows of M    -> out offset 32768
// ---------------------------------------------------------------------------
__global__ void __launch_bounds__(256)
softargmax_kernel(float* __restrict__ out)
{
    __shared__ float gtab[64];
    __shared__ float redf[8];
    __shared__ int   redi[8];
    __shared__ float bc[2];
    __shared__ float r3[3][8];

    const int pos = blockIdx.x;
    const int b   = blockIdx.y;
    const int dir = blockIdx.z;
    const int tid = threadIdx.x;
    const int lane = tid & 31, wid = tid >> 5;

    const float* row = (dir == 0 ? g_MT : g_M) + ((size_t)b * HW + pos) * HW;

    if (tid < 64) gtab[tid] = expf(-(float)(tid * tid) * (1.0f / 50.0f));

    // ---- pass 1: load to registers + sum of squares
    float xr[16];
    float ss = 0.f;
#pragma unroll
    for (int s = 0; s < 16; ++s) {
        float x = row[tid + s * 256];
        xr[s] = x;
        ss = fmaf(x, x, ss);
    }
    for (int o = 16; o; o >>= 1) ss += __shfl_down_sync(0xffffffffu, ss, o);
    if (lane == 0) redf[wid] = ss;
    __syncthreads();
    if (wid == 0) {
        float v = (lane < 8) ? redf[lane] : 0.f;
        for (int o = 4; o; o >>= 1) v += __shfl_down_sync(0xffffffffu, v, o);
        if (lane == 0) bc[0] = rsqrtf(v + 1e-6f);
    }
    __syncthreads();
    const float invn = bc[0];

    // ---- pass 2: argmax (first occurrence on ties)
    float bvv = -1.f; int bj = HW;
#pragma unroll
    for (int s = 0; s < 16; ++s) {
        float x = xr[s];
        int j = tid + s * 256;
        if (x > bvv) { bvv = x; bj = j; }   // j ascending within thread
    }
    for (int o = 16; o; o >>= 1) {
        float ov = __shfl_down_sync(0xffffffffu, bvv, o);
        int   oj = __shfl_down_sync(0xffffffffu, bj,  o);
        if (ov > bvv || (ov == bvv && oj < bj)) { bvv = ov; bj = oj; }
    }
    __syncthreads();                 // redf reuse safety
    if (lane == 0) { redf[wid] = bvv; redi[wid] = bj; }
    __syncthreads();
    if (tid == 0) {
        float bestv = redf[0]; int bestj = redi[0];
        for (int q = 1; q < 8; ++q)
            if (redf[q] > bestv || (redf[q] == bestv && redi[q] < bestj)) {
                bestv = redf[q]; bestj = redi[q];
            }
        redi[0] = bestj;
    }
    __syncthreads();
    const int amax = redi[0];
    const int ax = amax & 63, ay = amax >> 6;

    // ---- pass 3: c = gauss * normalized value; track max.
    // gauss < 1e-6 => mark with sentinel -1 (treated as e = e0 in pass 4;
    // error bound ~3e-5 on output coords).
    float cm = -1.f;
#pragma unroll
    for (int s = 0; s < 16; ++s) {
        int j = tid + s * 256;
        int dx = (j & 63) - ax; dx = dx < 0 ? -dx : dx;
        int dy = (j >> 6) - ay; dy = dy < 0 ? -dy : dy;
        float g = gtab[dx] * gtab[dy];
        float c = (g < 1e-6f) ? -1.f : g * xr[s] * invn;
        xr[s] = c;
        cm = fmaxf(cm, c);
    }
    for (int o = 16; o; o >>= 1) cm = fmaxf(cm, __shfl_down_sync(0xffffffffu, cm, o));
    __syncthreads();
    if (lane == 0) redf[wid] = cm;
    __syncthreads();
    if (wid == 0) {
        float v = (lane < 8) ? redf[lane] : -1.f;
        for (int o = 4; o; o >>= 1) v = fmaxf(v, __shfl_down_sync(0xffffffffu, v, o));
        if (lane == 0) bc[1] = v;
    }
    __syncthreads();
    const float m  = bc[1];
    const float e0 = __expf(-50.f * m);

    // ---- pass 4: stable softmax + soft-argmax sums.
    // Skipped (sentinel) elements contribute e0 each: sum(xn)=sum(yn)=0 over
    // the full grid, so they only add 4096*e0 to the denominator.
    float se = 0.f, sx = 0.f, sy = 0.f;
#pragma unroll
    for (int s = 0; s < 16; ++s) {
        float c = xr[s];
        if (c >= 0.f) {
            int j = tid + s * 256;
            float e = __expf(50.f * (c - m)) - e0;
            float xn = fmaf((float)(j & 63), 2.f / 63.f, -1.f);
            float yn = fmaf((float)(j >> 6), 2.f / 63.f, -1.f);
            se += e;
            sx = fmaf(e, xn, sx);
            sy = fmaf(e, yn, sy);
        }
    }
    for (int o = 16; o; o >>= 1) {
        se += __shfl_down_sync(0xffffffffu, se, o);
        sx += __shfl_down_sync(0xffffffffu, sx, o);
        sy += __shfl_down_sync(0xffffffffu, sy, o);
    }
    if (lane == 0) { r3[0][wid] = se; r3[1][wid] = sx; r3[2][wid] = sy; }
    __syncthreads();
    if (tid == 0) {
        float tse = 0.f, tsx = 0.f, tsy = 0.f;
        for (int q = 0; q < 8; ++q) { tse += r3[0][q]; tsx += r3[1][q]; tsy += r3[2][q]; }
        float denom = tse + 4096.f * e0;
        float gx = tsx / denom;
        float gy = tsy / denom;
        // grid layout (b, h, w, 2); s2t at offset 0, t2s at 32768
        size_t ob = (size_t)dir * 32768 + (((size_t)b * 64 + (pos >> 6)) * 64 + (pos & 63)) * 2;
        out[ob]     = gx;
        out[ob + 1] = gy;
    }
}

// ---------------------------------------------------------------------------
// Kernel 4: flow outputs are exactly zero (grid_x - grid_x).
// ---------------------------------------------------------------------------
__global__ void zero_kernel(float* __restrict__ out)
{
    int i = blockIdx.x * blockDim.x + threadIdx.x;   // 0..32767
    int base = (i < 16384) ? 16384 : 49152;
    out[base + (i & 16383)] = 0.f;
}

// ---------------------------------------------------------------------------
extern "C" void kernel_launch(void* const* d_in, const int* in_sizes, int n_in,
                              void* d_out, int out_size)
{
    const float* s3 = (const float*)d_in[0];
    const float* t3 = (const float*)d_in[1];
    const float* s4 = (const float*)d_in[2];
    const float* t4 = (const float*)d_in[3];
    float* out = (float*)d_out;

    norm_kernel<<<dim3(32, 4), 256>>>(s3, t3, s4, t4);
    gemm_kernel<0><<<dim3(32, 32, NB), 256>>>(t3, s3, 1024);
    gemm_kernel<1><<<dim3(32, 32, NB), 256>>>(t4, s4, 2048);
    softargmax_kernel<<<dim3(HW, NB, 2), 256>>>(out);
    zero_kernel<<<64, 512>>>(out);
}